// round 3
// baseline (speedup 1.0000x reference)
#include <cuda_runtime.h>
#include <math.h>

#define EPS_BN 1e-5f
#define EPS_LN 1e-5f

#define NQ   1024
#define NSUP 24
#define NTOT 1048

// ---------------------------------------------------------------------------
// Device-global scratch (no allocations anywhere)
// ---------------------------------------------------------------------------
static __device__ float g_convbuf[429260800];  // max: 1048*64*80*80 (L1 conv out)
static __device__ float g_bufA[107315200];     // 1048*64*40*40
static __device__ float g_bufB[26828800];      // 1048*64*20*20
static __device__ float g_stats[512];          // (group,oc) -> {sum, sumsq}
static __device__ float g_scale[256];          // (group,oc)
static __device__ float g_shift[256];
static __device__ float g_wt[112320];          // transposed weights, all layers
static __device__ float g_emb[NTOT * 64];
static __device__ float g_sn[3 * 64];

#define WT1 0
#define WT2 1728
#define WT3 38592
#define WT4 75456

__device__ __forceinline__ int bn_group(int n) {
    return (n < NQ) ? 0 : (1 + ((n - NQ) >> 3));
}

// ---------------------------------------------------------------------------
// Weight transpose: [oc][ic][3][3] -> [ic][k][oc]
// ---------------------------------------------------------------------------
__global__ void tw_k(const float* __restrict__ w, int CIN, int off) {
    int idx = blockIdx.x * 256 + threadIdx.x;
    int tot = CIN * 9 * 64;
    if (idx >= tot) return;
    int oc = idx & 63;
    int kk = (idx >> 6) % 9;
    int ic = idx / (9 * 64);
    g_wt[off + idx] = w[(oc * CIN + ic) * 9 + kk];
}

__global__ void zstats_k() {
    g_stats[threadIdx.x] = 0.f;
}

// ---------------------------------------------------------------------------
// Direct conv 3x3 pad1 + fused BN-stat reduction.
// Block: 256 threads = 4 oc-groups x 64 pixels (8x8 tile). 16 oc/thread.
// Writes conv output to g_convbuf, atomically accumulates per-(group,oc)
// sum/sumsq via warp-shfl + smem combine.
// ---------------------------------------------------------------------------
template <int L>
__global__ void __launch_bounds__(256, 2)
conv_k(const float* __restrict__ in1, const float* __restrict__ in2) {
    constexpr int CIN  = (L == 1) ? 3 : 64;
    constexpr int H    = (L == 1) ? 80 : (L == 2) ? 40 : (L == 3) ? 20 : 10;
    constexpr int ICC  = (L == 1) ? 3 : 8;
    constexpr int TH   = 8, TW = 8;
    constexpr int SR   = TH + 2, SC = TW + 2;
    constexpr int WOFF = (L == 1) ? WT1 : (L == 2) ? WT2 : (L == 3) ? WT3 : WT4;
    constexpr int TILESX = (H + TW - 1) / TW;

    __shared__ float s_in[ICC * SR * SC];
    __shared__ float s_w[ICC * 9 * 64];
    __shared__ float s_red[8][32];

    const int n    = blockIdx.y;
    const int tile = blockIdx.x;
    const int y0   = (tile / TILESX) * TH;
    const int x0   = (tile % TILESX) * TW;
    const int tid  = threadIdx.x;
    const int ocg  = tid >> 6;
    const int pix  = tid & 63;
    const int py   = pix >> 3;
    const int px   = pix & 7;

    const float* gin;
    if constexpr (L == 1) {
        gin = (n < NQ) ? in1 + (size_t)n * (3 * 80 * 80)
                       : in2 + (size_t)(n - NQ) * (3 * 80 * 80);
    } else if constexpr (L == 2) {
        gin = g_bufA + (size_t)n * (64 * 40 * 40);
    } else if constexpr (L == 3) {
        gin = g_bufB + (size_t)n * (64 * 20 * 20);
    } else {
        gin = g_bufA + (size_t)n * (64 * 10 * 10);
    }

    float acc[16];
#pragma unroll
    for (int j = 0; j < 16; j++) acc[j] = 0.f;

    for (int ic0 = 0; ic0 < CIN; ic0 += ICC) {
        // load input chunk (zero-padded halo)
        for (int idx = tid; idx < ICC * SR * SC; idx += 256) {
            int c   = idx % SC;
            int r   = (idx / SC) % SR;
            int icl = idx / (SC * SR);
            int gy = y0 + r - 1, gx = x0 + c - 1;
            float v = 0.f;
            if (gy >= 0 && gy < H && gx >= 0 && gx < H)
                v = gin[((size_t)(ic0 + icl) * H + gy) * H + gx];
            s_in[idx] = v;
        }
        // load weight chunk (already transposed: [ic][k][oc])
        for (int idx = tid; idx < ICC * 9 * 64; idx += 256)
            s_w[idx] = g_wt[WOFF + ic0 * 9 * 64 + idx];
        __syncthreads();

#pragma unroll
        for (int icl = 0; icl < ICC; icl++) {
#pragma unroll
            for (int kk = 0; kk < 9; kk++) {
                int ky = kk / 3, kx = kk % 3;
                float v = s_in[(icl * SR + py + ky) * SC + px + kx];
                const float4* wp = reinterpret_cast<const float4*>(
                    &s_w[(icl * 9 + kk) * 64 + ocg * 16]);
                float4 w0 = wp[0], w1 = wp[1], w2 = wp[2], w3 = wp[3];
                acc[0]  += v * w0.x; acc[1]  += v * w0.y;
                acc[2]  += v * w0.z; acc[3]  += v * w0.w;
                acc[4]  += v * w1.x; acc[5]  += v * w1.y;
                acc[6]  += v * w1.z; acc[7]  += v * w1.w;
                acc[8]  += v * w2.x; acc[9]  += v * w2.y;
                acc[10] += v * w2.z; acc[11] += v * w2.w;
                acc[12] += v * w3.x; acc[13] += v * w3.y;
                acc[14] += v * w3.z; acc[15] += v * w3.w;
            }
        }
        __syncthreads();
    }

    const bool valid = (y0 + py) < H && (x0 + px) < H;
    const int g = bn_group(n);
    float* cb = g_convbuf + (size_t)n * 64 * H * H;

#pragma unroll
    for (int j = 0; j < 16; j++) {
        float v = valid ? acc[j] : 0.f;
        if (valid)
            cb[((ocg * 16 + j) * H + (y0 + py)) * H + (x0 + px)] = v;
        float s = v, q = v * v;
#pragma unroll
        for (int o = 16; o > 0; o >>= 1) {
            s += __shfl_down_sync(0xffffffffu, s, o);
            q += __shfl_down_sync(0xffffffffu, q, o);
        }
        if ((tid & 31) == 0) {
            s_red[tid >> 5][j]      = s;
            s_red[tid >> 5][16 + j] = q;
        }
    }
    __syncthreads();
    if (tid < 128) {
        int gg = tid >> 5;   // ocg
        int j  = tid & 31;   // 0..15 sum, 16..31 sumsq
        float v = s_red[2 * gg][j] + s_red[2 * gg + 1][j];
        int oc = gg * 16 + (j & 15);
        atomicAdd(&g_stats[(g * 64 + oc) * 2 + (j >> 4)], v);
    }
}

// ---------------------------------------------------------------------------
// BN finalize: stats -> per-(group,oc) scale/shift
// ---------------------------------------------------------------------------
__global__ void finalize_k(const float* __restrict__ gam,
                           const float* __restrict__ bet, int H) {
    int t   = threadIdx.x;          // 256 = 4 groups x 64 oc
    int grp = t >> 6, oc = t & 63;
    float cnt = (grp == 0 ? (float)NQ : 8.f) * (float)(H * H);
    float s = g_stats[t * 2], q = g_stats[t * 2 + 1];
    float m = s / cnt;
    float v = q / cnt - m * m;
    float sc = gam[oc] * rsqrtf(v + EPS_BN);
    g_scale[t] = sc;
    g_shift[t] = bet[oc] - m * sc;
}

// ---------------------------------------------------------------------------
// BN apply + LeakyReLU(0.2) + maxpool2
// ---------------------------------------------------------------------------
template <int L>
__global__ void bnpool_k() {
    constexpr int H  = (L == 1) ? 80 : (L == 2) ? 40 : (L == 3) ? 20 : 10;
    constexpr int Wp = H / 2;
    const int total  = NTOT * 64 * Wp * Wp;
    int idx = blockIdx.x * 256 + threadIdx.x;
    if (idx >= total) return;

    int px = idx % Wp;
    int t  = idx / Wp;
    int py = t % Wp; t /= Wp;
    int oc = t & 63;
    int n  = t >> 6;
    int g  = bn_group(n);
    float sc = g_scale[g * 64 + oc];
    float sh = g_shift[g * 64 + oc];

    const float* p = g_convbuf + (((size_t)n * 64 + oc) * H + 2 * py) * H + 2 * px;
    float a = p[0], b = p[1], c = p[H], d = p[H + 1];
    a = fmaf(a, sc, sh); a = a > 0.f ? a : 0.2f * a;
    b = fmaf(b, sc, sh); b = b > 0.f ? b : 0.2f * b;
    c = fmaf(c, sc, sh); c = c > 0.f ? c : 0.2f * c;
    d = fmaf(d, sc, sh); d = d > 0.f ? d : 0.2f * d;
    float m = fmaxf(fmaxf(a, b), fmaxf(c, d));

    float* out;
    if constexpr (L == 1)      out = g_bufA;
    else if constexpr (L == 2) out = g_bufB;
    else if constexpr (L == 3) out = g_bufA;
    else                       out = g_bufB;
    out[idx] = m;
}

// ---------------------------------------------------------------------------
// Embedding: maxpool5 over [n][oc][5][5] -> g_emb[n][oc]
// ---------------------------------------------------------------------------
__global__ void embed_k() {
    int idx = blockIdx.x * 256 + threadIdx.x;
    if (idx >= NTOT * 64) return;
    const float* p = g_bufB + (size_t)idx * 25;
    float m = p[0];
#pragma unroll
    for (int i = 1; i < 25; i++) m = fmaxf(m, p[i]);
    g_emb[idx] = m;
}

// ---------------------------------------------------------------------------
// Prototype attention + layernorm + row-normalize -> g_sn[3][64]
// Single block, 64 threads.
// ---------------------------------------------------------------------------
__global__ void attn_k(const float* __restrict__ wq, const float* __restrict__ wk,
                       const float* __restrict__ wv, const float* __restrict__ fcw,
                       const float* __restrict__ fcb, const float* __restrict__ lng,
                       const float* __restrict__ lnb) {
    __shared__ float P[3][64], Q[3][64], K[3][64], V[3][64], O[3][64];
    __shared__ float A[3][3], MU[3], SG[3], NR[3];
    int t = threadIdx.x;  // 0..63

    for (int l = 0; l < 3; l++) {
        float s = 0.f;
        for (int i = 0; i < 8; i++) s += g_emb[(NQ + l * 8 + i) * 64 + t];
        P[l][t] = s * 0.125f;
    }
    __syncthreads();

    for (int l = 0; l < 3; l++) {
        float q = 0.f, k = 0.f, v = 0.f;
        for (int d = 0; d < 64; d++) {
            float p = P[l][d];
            q += p * wq[t * 64 + d];
            k += p * wk[t * 64 + d];
            v += p * wv[t * 64 + d];
        }
        Q[l][t] = q; K[l][t] = k; V[l][t] = v;
    }
    __syncthreads();

    if (t < 9) {
        int qi = t / 3, ki = t % 3;
        float a = 0.f;
        for (int d = 0; d < 64; d++) a += Q[qi][d] * K[ki][d];
        A[qi][ki] = a * 0.125f;  // 1/sqrt(64)
    }
    __syncthreads();
    if (t < 3) {
        float m = fmaxf(A[t][0], fmaxf(A[t][1], A[t][2]));
        float e0 = expf(A[t][0] - m), e1 = expf(A[t][1] - m), e2 = expf(A[t][2] - m);
        float inv = 1.f / (e0 + e1 + e2);
        A[t][0] = e0 * inv; A[t][1] = e1 * inv; A[t][2] = e2 * inv;
    }
    __syncthreads();

    for (int l = 0; l < 3; l++)
        O[l][t] = A[l][0] * V[0][t] + A[l][1] * V[1][t] + A[l][2] * V[2][t];
    __syncthreads();

    for (int l = 0; l < 3; l++) {
        float o = fcb[t];
        for (int d = 0; d < 64; d++) o += O[l][d] * fcw[t * 64 + d];
        Q[l][t] = o + P[l][t];  // residual, reuse Q
    }
    __syncthreads();

    if (t < 3) {
        float s = 0.f, q = 0.f;
        for (int d = 0; d < 64; d++) { float x = Q[t][d]; s += x; q += x * x; }
        float m = s / 64.f;
        MU[t] = m;
        SG[t] = rsqrtf(q / 64.f - m * m + EPS_LN);
    }
    __syncthreads();

    for (int l = 0; l < 3; l++)
        K[l][t] = (Q[l][t] - MU[l]) * SG[l] * lng[t] + lnb[t];  // reuse K
    __syncthreads();

    if (t < 3) {
        float q = 0.f;
        for (int d = 0; d < 64; d++) q += K[t][d] * K[t][d];
        NR[t] = rsqrtf(q);
    }
    __syncthreads();

    for (int l = 0; l < 3; l++)
        g_sn[l * 64 + t] = K[l][t] * NR[l];
}

// ---------------------------------------------------------------------------
// Cosine similarity: out[n][k] = (emb[n]/||emb[n]||) . sn[k]
// One warp per query row.
// ---------------------------------------------------------------------------
__global__ void cos_k(float* __restrict__ out) {
    int warp = threadIdx.x >> 5, lane = threadIdx.x & 31;
    int n = blockIdx.x * 4 + warp;
    if (n >= NQ) return;
    float v1 = g_emb[n * 64 + lane];
    float v2 = g_emb[n * 64 + 32 + lane];
    float ss = v1 * v1 + v2 * v2;
#pragma unroll
    for (int o = 16; o > 0; o >>= 1) ss += __shfl_xor_sync(0xffffffffu, ss, o);
    float rn = rsqrtf(ss);
#pragma unroll
    for (int k = 0; k < 3; k++) {
        float d = v1 * g_sn[k * 64 + lane] + v2 * g_sn[k * 64 + 32 + lane];
#pragma unroll
        for (int o = 16; o > 0; o >>= 1) d += __shfl_xor_sync(0xffffffffu, d, o);
        if (lane == 0) out[n * 3 + k] = d * rn;
    }
}

// ---------------------------------------------------------------------------
// Launch
// ---------------------------------------------------------------------------
extern "C" void kernel_launch(void* const* d_in, const int* in_sizes, int n_in,
                              void* d_out, int out_size) {
    const float* input1  = (const float*)d_in[0];
    const float* input2  = (const float*)d_in[1];
    const float* conv1_w = (const float*)d_in[2];
    const float* conv2_w = (const float*)d_in[3];
    const float* conv3_w = (const float*)d_in[4];
    const float* conv4_w = (const float*)d_in[5];
    const float* bn_g[4] = {(const float*)d_in[6], (const float*)d_in[8],
                            (const float*)d_in[10], (const float*)d_in[12]};
    const float* bn_b[4] = {(const float*)d_in[7], (const float*)d_in[9],
                            (const float*)d_in[11], (const float*)d_in[13]};
    const float* wq   = (const float*)d_in[14];
    const float* wk   = (const float*)d_in[15];
    const float* wv   = (const float*)d_in[16];
    const float* fc_w = (const float*)d_in[17];
    const float* fc_b = (const float*)d_in[18];
    const float* ln_g = (const float*)d_in[19];
    const float* ln_b = (const float*)d_in[20];
    float* out = (float*)d_out;

    // weight transpose
    tw_k<<<(3 * 9 * 64 + 255) / 256, 256>>>(conv1_w, 3, WT1);
    tw_k<<<(64 * 9 * 64 + 255) / 256, 256>>>(conv2_w, 64, WT2);
    tw_k<<<(64 * 9 * 64 + 255) / 256, 256>>>(conv3_w, 64, WT3);
    tw_k<<<(64 * 9 * 64 + 255) / 256, 256>>>(conv4_w, 64, WT4);

    // Layer 1: 80x80 -> pool 40x40
    zstats_k<<<1, 512>>>();
    conv_k<1><<<dim3(100, NTOT), 256>>>(input1, input2);
    finalize_k<<<1, 256>>>(bn_g[0], bn_b[0], 80);
    { int tot = NTOT * 64 * 40 * 40; bnpool_k<1><<<(tot + 255) / 256, 256>>>(); }

    // Layer 2: 40x40 -> pool 20x20
    zstats_k<<<1, 512>>>();
    conv_k<2><<<dim3(25, NTOT), 256>>>(nullptr, nullptr);
    finalize_k<<<1, 256>>>(bn_g[1], bn_b[1], 40);
    { int tot = NTOT * 64 * 20 * 20; bnpool_k<2><<<(tot + 255) / 256, 256>>>(); }

    // Layer 3: 20x20 -> pool 10x10
    zstats_k<<<1, 512>>>();
    conv_k<3><<<dim3(9, NTOT), 256>>>(nullptr, nullptr);
    finalize_k<<<1, 256>>>(bn_g[2], bn_b[2], 20);
    { int tot = NTOT * 64 * 10 * 10; bnpool_k<3><<<(tot + 255) / 256, 256>>>(); }

    // Layer 4: 10x10 -> pool 5x5
    zstats_k<<<1, 512>>>();
    conv_k<4><<<dim3(4, NTOT), 256>>>(nullptr, nullptr);
    finalize_k<<<1, 256>>>(bn_g[3], bn_b[3], 10);
    { int tot = NTOT * 64 * 5 * 5; bnpool_k<4><<<(tot + 255) / 256, 256>>>(); }

    // embedding (maxpool5)
    embed_k<<<(NTOT * 64 + 255) / 256, 256>>>();

    // prototype attention + LN + normalize
    attn_k<<<1, 64>>>(wq, wk, wv, fc_w, fc_b, ln_g, ln_b);

    // cosine similarity -> [1024, 3]
    cos_k<<<256, 128>>>(out);
}

// round 6
// speedup vs baseline: 2.3346x; 2.3346x over previous
#include <cuda_runtime.h>
#include <cuda_bf16.h>
#include <math.h>
#include <stdint.h>

#define EPS_BN 1e-5f
#define EPS_LN 1e-5f
#define NQ   1024
#define NTOT 1048

// ======================= helpers =======================
__device__ __forceinline__ uint32_t smem_u32(const void* p) {
    uint32_t a;
    asm("{ .reg .u64 t; cvta.to.shared.u64 t, %1; cvt.u32.u64 %0, t; }" : "=r"(a) : "l"(p));
    return a;
}
__device__ __forceinline__ void ldsm4(uint32_t* r, uint32_t addr) {
    asm volatile("ldmatrix.sync.aligned.m8n8.x4.shared.b16 {%0,%1,%2,%3}, [%4];"
                 : "=r"(r[0]), "=r"(r[1]), "=r"(r[2]), "=r"(r[3]) : "r"(addr) : "memory");
}
__device__ __forceinline__ void mma16816(float* d, const uint32_t* a, uint32_t b0, uint32_t b1) {
    asm volatile("mma.sync.aligned.m16n8k16.row.col.f32.bf16.bf16.f32 "
                 "{%0,%1,%2,%3}, {%4,%5,%6,%7}, {%8,%9}, {%0,%1,%2,%3};"
                 : "+f"(d[0]), "+f"(d[1]), "+f"(d[2]), "+f"(d[3])
                 : "r"(a[0]), "r"(a[1]), "r"(a[2]), "r"(a[3]), "r"(b0), "r"(b1));
}

// ======================= scratch (NHWC) =======================
static __device__ float g_c1out[429260800];            // 1048*80*80*64
static __device__ float g_c2out[107315200];
static __device__ float g_c3out[26828800];
static __device__ float g_c4out[6707200];
static __device__ unsigned short g_inhi[107315200];    // bf16 hi image (reused per layer)
static __device__ unsigned short g_inlo[107315200];    // bf16 lo image
static __device__ float g_stats[512];
static __device__ float g_scale[256];
static __device__ float g_shift[256];
static __device__ float g_wt1[1728];
static __device__ __align__(16) unsigned short g_wF2[73728];  // frag-packed weights (9*2*4*32*8 entries x 4)
static __device__ __align__(16) unsigned short g_wF3[73728];
static __device__ __align__(16) unsigned short g_wF4[73728];
static __device__ float g_emb[NTOT * 64];
static __device__ float g_sn[3 * 64];

__device__ __forceinline__ int bn_group(int n) { return (n < NQ) ? 0 : (1 + ((n - NQ) >> 3)); }

// ======================= weight prep =======================
__global__ void tw1_k(const float* __restrict__ w) {
    int idx = blockIdx.x * 256 + threadIdx.x;
    if (idx >= 1728) return;
    int oc = idx & 63, kk = (idx >> 6) % 9, ic = idx / 576;
    g_wt1[idx] = w[(oc * 3 + ic) * 9 + kk];
}
// Pack conv_w [oc][ic][3][3] into mma B-fragment order:
// entry e -> [s][combo][kstep][lane][nb], 4 ushorts {b0.lo,b0.hi,b1.lo,b1.hi}
__global__ void wcvt_k(const float* __restrict__ w, unsigned short* __restrict__ dst) {
    int e = blockIdx.x * 256 + threadIdx.x;
    if (e >= 18432) return;
    int nb   = e & 7;
    int lane = (e >> 3) & 31;
    int kk   = (e >> 8) & 3;
    int cmb  = (e >> 10) & 1;
    int s    = e >> 11;
    int n = nb * 8 + (lane >> 2);
#pragma unroll
    for (int j = 0; j < 2; j++)
#pragma unroll
        for (int h = 0; h < 2; h++) {
            int k = kk * 16 + (lane & 3) * 2 + j * 8 + h;
            float x = w[(n * 64 + k) * 9 + s];
            __nv_bfloat16 hi = __float2bfloat16(x);
            unsigned short v;
            if (cmb == 0) v = __bfloat16_as_ushort(hi);
            else          v = __bfloat16_as_ushort(__float2bfloat16(x - __bfloat162float(hi)));
            dst[e * 4 + j * 2 + h] = v;
        }
}
__global__ void zstats_k() { g_stats[threadIdx.x] = 0.f; }

// ======================= L1: FFMA conv, NHWC out + fused stats =======================
__global__ void __launch_bounds__(256, 2) conv1_k(const float* __restrict__ in1, const float* __restrict__ in2) {
    constexpr int H = 80, SR = 10, SC = 10;
    __shared__ float s_in[3 * SR * SC];
    __shared__ float s_w[1728];
    __shared__ float s_red[8][32];
    const int n = blockIdx.y, tile = blockIdx.x;
    const int y0 = (tile / 10) * 8, x0 = (tile % 10) * 8;
    const int tid = threadIdx.x, ocg = tid >> 6, pix = tid & 63;
    const int py = pix >> 3, px = pix & 7;
    const float* gin = (n < NQ) ? in1 + (size_t)n * 19200 : in2 + (size_t)(n - NQ) * 19200;

    for (int idx = tid; idx < 3 * SR * SC; idx += 256) {
        int c = idx % SC, r = (idx / SC) % SR, ic = idx / 100;
        int gy = y0 + r - 1, gx = x0 + c - 1;
        float v = 0.f;
        if (gy >= 0 && gy < H && gx >= 0 && gx < H) v = gin[((size_t)ic * H + gy) * H + gx];
        s_in[idx] = v;
    }
    for (int idx = tid; idx < 1728; idx += 256) s_w[idx] = g_wt1[idx];
    __syncthreads();

    float acc[16];
#pragma unroll
    for (int j = 0; j < 16; j++) acc[j] = 0.f;
#pragma unroll
    for (int ic = 0; ic < 3; ic++)
#pragma unroll
        for (int kk = 0; kk < 9; kk++) {
            float v = s_in[(ic * SR + py + kk / 3) * SC + px + kk % 3];
            const float4* wp = reinterpret_cast<const float4*>(&s_w[(ic * 9 + kk) * 64 + ocg * 16]);
            float4 w0 = wp[0], w1 = wp[1], w2 = wp[2], w3 = wp[3];
            acc[0]+=v*w0.x; acc[1]+=v*w0.y; acc[2]+=v*w0.z; acc[3]+=v*w0.w;
            acc[4]+=v*w1.x; acc[5]+=v*w1.y; acc[6]+=v*w1.z; acc[7]+=v*w1.w;
            acc[8]+=v*w2.x; acc[9]+=v*w2.y; acc[10]+=v*w2.z; acc[11]+=v*w2.w;
            acc[12]+=v*w3.x; acc[13]+=v*w3.y; acc[14]+=v*w3.z; acc[15]+=v*w3.w;
        }

    float* cb = g_c1out + (((size_t)n * H + (y0 + py)) * H + (x0 + px)) * 64 + ocg * 16;
#pragma unroll
    for (int j = 0; j < 16; j += 4)
        *reinterpret_cast<float4*>(cb + j) = make_float4(acc[j], acc[j+1], acc[j+2], acc[j+3]);

    const int g = bn_group(n);
#pragma unroll
    for (int j = 0; j < 16; j++) {
        float s = acc[j], q = acc[j] * acc[j];
#pragma unroll
        for (int o = 16; o > 0; o >>= 1) {
            s += __shfl_down_sync(0xffffffffu, s, o);
            q += __shfl_down_sync(0xffffffffu, q, o);
        }
        if ((tid & 31) == 0) { s_red[tid >> 5][j] = s; s_red[tid >> 5][16 + j] = q; }
    }
    __syncthreads();
    if (tid < 128) {
        int gg = tid >> 5, j = tid & 31;
        float v = s_red[2 * gg][j] + s_red[2 * gg + 1][j];
        atomicAdd(&g_stats[(g * 64 + gg * 16 + (j & 15)) * 2 + (j >> 4)], v);
    }
}

// ======================= tensor conv L2-L4 via mma.sync bf16 hi/lo =======================
template <int H>
__global__ void __launch_bounds__(256) conv_t(
    const unsigned short* __restrict__ inhi, const unsigned short* __restrict__ inlo,
    float* __restrict__ outbuf, const unsigned short* __restrict__ wBf)
{
    constexpr int NPIX = H * H, W2 = H + 2;
    constexpr int NT = (NPIX + 127) / 128;
    constexpr int RB = (127 + H - 1) / H + 3;
    constexpr int SLOTS = RB * W2;
    constexpr int BANDB = SLOTS * 128;
    extern __shared__ __align__(16) unsigned char smem[];
    const uint32_t sb = smem_u32(smem);
    const int tid = threadIdx.x, lane = tid & 31, wid = tid >> 5;
    const int warp_m = wid & 3, warp_n = wid >> 2;
    const int n = blockIdx.x;
    const unsigned short* ghi = inhi + (size_t)n * NPIX * 64;
    const unsigned short* glo = inlo + (size_t)n * NPIX * 64;
    float* gout = outbuf + (size_t)n * NPIX * 64;

    for (int t = 0; t < NT; t++) {
        __syncthreads();
        const int m0 = t * 128, ytile = m0 / H;
        for (int sl = tid; sl < SLOTS; sl += 256) {
            int r = sl / W2, c = sl - r * W2;
            int y = ytile + r - 1, x = c - 1;
            bool v = ((unsigned)y < (unsigned)H) && ((unsigned)x < (unsigned)H);
            const uint4* sh = reinterpret_cast<const uint4*>(ghi + (size_t)(y * H + x) * 64);
            const uint4* so = reinterpret_cast<const uint4*>(glo + (size_t)(y * H + x) * 64);
#pragma unroll
            for (int ch = 0; ch < 8; ch++) {
                uint4 dh = v ? sh[ch] : make_uint4(0, 0, 0, 0);
                uint4 dl = v ? so[ch] : make_uint4(0, 0, 0, 0);
                uint32_t off = (uint32_t)sl * 128 + (uint32_t)((ch ^ (sl & 7)) << 4);
                *reinterpret_cast<uint4*>(smem + off) = dh;
                *reinterpret_cast<uint4*>(smem + BANDB + off) = dl;
            }
        }
        __syncthreads();

        int bp[2];
#pragma unroll
        for (int mb = 0; mb < 2; mb++) {
            int p = m0 + warp_m * 32 + mb * 16 + (lane & 15);
            int y = p / H, x = p - y * H;
            bp[mb] = (y - ytile + 1) * W2 + x + 1;
        }
        const int khalf = lane >> 4;

        float acc[2][4][4];
#pragma unroll
        for (int a = 0; a < 2; a++)
#pragma unroll
            for (int b = 0; b < 4; b++)
#pragma unroll
                for (int c = 0; c < 4; c++) acc[a][b][c] = 0.f;

#pragma unroll 1
        for (int s = 0; s < 9; s++) {
            const int so9 = (s / 3 - 1) * W2 + (s % 3 - 1);
            const int b0 = bp[0] + so9, b1 = bp[1] + so9;
#pragma unroll
            for (int kk = 0; kk < 4; kk++) {
                const int ch = kk * 2 + khalf;
                uint32_t off0 = (uint32_t)b0 * 128 + (uint32_t)((ch ^ (b0 & 7)) << 4);
                uint32_t off1 = (uint32_t)b1 * 128 + (uint32_t)((ch ^ (b1 & 7)) << 4);
                uint32_t ah0[4], ah1[4], al0[4], al1[4];
                ldsm4(ah0, sb + off0);
                ldsm4(ah1, sb + off1);
                ldsm4(al0, sb + BANDB + off0);
                ldsm4(al1, sb + BANDB + off1);

                const unsigned short* bs0 = wBf + ((((s * 2 + 0) * 4 + kk) * 32 + lane) * 32 + warp_n * 16);
                const unsigned short* bs1 = wBf + ((((s * 2 + 1) * 4 + kk) * 32 + lane) * 32 + warp_n * 16);
                uint4 h0 = *reinterpret_cast<const uint4*>(bs0);
                uint4 h1 = *reinterpret_cast<const uint4*>(bs0 + 8);
                uint4 l0 = *reinterpret_cast<const uint4*>(bs1);
                uint4 l1 = *reinterpret_cast<const uint4*>(bs1 + 8);
                uint32_t bh[8] = {h0.x, h0.y, h0.z, h0.w, h1.x, h1.y, h1.z, h1.w};
                uint32_t bl[8] = {l0.x, l0.y, l0.z, l0.w, l1.x, l1.y, l1.z, l1.w};

#pragma unroll
                for (int nb = 0; nb < 4; nb++) {
                    mma16816(acc[0][nb], ah0, bh[nb * 2], bh[nb * 2 + 1]);
                    mma16816(acc[1][nb], ah1, bh[nb * 2], bh[nb * 2 + 1]);
                }
#pragma unroll
                for (int nb = 0; nb < 4; nb++) {
                    mma16816(acc[0][nb], ah0, bl[nb * 2], bl[nb * 2 + 1]);
                    mma16816(acc[1][nb], ah1, bl[nb * 2], bl[nb * 2 + 1]);
                }
#pragma unroll
                for (int nb = 0; nb < 4; nb++) {
                    mma16816(acc[0][nb], al0, bh[nb * 2], bh[nb * 2 + 1]);
                    mma16816(acc[1][nb], al1, bh[nb * 2], bh[nb * 2 + 1]);
                }
            }
        }

#pragma unroll
        for (int mb = 0; mb < 2; mb++) {
            int p0 = m0 + warp_m * 32 + mb * 16 + (lane >> 2);
#pragma unroll
            for (int nb = 0; nb < 4; nb++) {
                int col = warp_n * 32 + nb * 8 + (lane & 3) * 2;
                if (p0 < NPIX)
                    *reinterpret_cast<float2*>(gout + (size_t)p0 * 64 + col) =
                        make_float2(acc[mb][nb][0], acc[mb][nb][1]);
                if (p0 + 8 < NPIX)
                    *reinterpret_cast<float2*>(gout + (size_t)(p0 + 8) * 64 + col) =
                        make_float2(acc[mb][nb][2], acc[mb][nb][3]);
            }
        }
    }
}

// ======================= stats over NHWC conv output =======================
template <int H>
__global__ void stats_k(const float* __restrict__ buf) {
    __shared__ float ss[4][64], qq[4][64];
    const int n = blockIdx.x, c = threadIdx.x & 63, sl = threadIdx.x >> 6;
    const float* p = buf + (size_t)n * H * H * 64;
    float s = 0.f, q = 0.f;
    for (int i = sl; i < H * H; i += 4) { float v = p[(size_t)i * 64 + c]; s += v; q += v * v; }
    ss[sl][c] = s; qq[sl][c] = q;
    __syncthreads();
    const int g = bn_group(n);
    if (threadIdx.x < 64)
        atomicAdd(&g_stats[(g * 64 + c) * 2], ss[0][c] + ss[1][c] + ss[2][c] + ss[3][c]);
    else if (threadIdx.x < 128) {
        int cc = threadIdx.x - 64;
        atomicAdd(&g_stats[(g * 64 + cc) * 2 + 1], qq[0][cc] + qq[1][cc] + qq[2][cc] + qq[3][cc]);
    }
}

__global__ void finalize_k(const float* __restrict__ gam, const float* __restrict__ bet, int H) {
    int t = threadIdx.x, grp = t >> 6, oc = t & 63;
    float cnt = (grp == 0 ? (float)NQ : 8.f) * (float)(H * H);
    float m = g_stats[t * 2] / cnt;
    float v = g_stats[t * 2 + 1] / cnt - m * m;
    float sc = gam[oc] * rsqrtf(v + EPS_BN);
    g_scale[t] = sc;
    g_shift[t] = bet[oc] - m * sc;
}

// ======================= BN + LReLU + pool2 -> bf16 hi/lo NHWC =======================
__device__ __forceinline__ float bnlr(float x, float sc, float sh) {
    x = fmaf(x, sc, sh);
    return x > 0.f ? x : 0.2f * x;
}
template <int HIN>
__global__ void bnpool_k(const float* __restrict__ in,
                         unsigned short* __restrict__ ohi, unsigned short* __restrict__ olo) {
    constexpr int HO = HIN / 2;
    int idx = blockIdx.x * 256 + threadIdx.x;
    if (idx >= NTOT * HO * HO * 16) return;
    int c4 = idx & 15, t = idx >> 4;
    int px = t % HO; t /= HO;
    int py = t % HO;
    int n = t / HO, g = bn_group(n);
    float4 sc = *reinterpret_cast<const float4*>(&g_scale[g * 64 + c4 * 4]);
    float4 sh = *reinterpret_cast<const float4*>(&g_shift[g * 64 + c4 * 4]);
    const float* p = in + (((size_t)n * HIN + 2 * py) * HIN + 2 * px) * 64 + c4 * 4;
    float4 a = *reinterpret_cast<const float4*>(p);
    float4 b = *reinterpret_cast<const float4*>(p + 64);
    float4 c = *reinterpret_cast<const float4*>(p + HIN * 64);
    float4 d = *reinterpret_cast<const float4*>(p + HIN * 64 + 64);
    float r[4];
    r[0] = fmaxf(fmaxf(bnlr(a.x,sc.x,sh.x), bnlr(b.x,sc.x,sh.x)), fmaxf(bnlr(c.x,sc.x,sh.x), bnlr(d.x,sc.x,sh.x)));
    r[1] = fmaxf(fmaxf(bnlr(a.y,sc.y,sh.y), bnlr(b.y,sc.y,sh.y)), fmaxf(bnlr(c.y,sc.y,sh.y), bnlr(d.y,sc.y,sh.y)));
    r[2] = fmaxf(fmaxf(bnlr(a.z,sc.z,sh.z), bnlr(b.z,sc.z,sh.z)), fmaxf(bnlr(c.z,sc.z,sh.z), bnlr(d.z,sc.z,sh.z)));
    r[3] = fmaxf(fmaxf(bnlr(a.w,sc.w,sh.w), bnlr(b.w,sc.w,sh.w)), fmaxf(bnlr(c.w,sc.w,sh.w), bnlr(d.w,sc.w,sh.w)));
    unsigned short h[4], l[4];
#pragma unroll
    for (int j = 0; j < 4; j++) {
        __nv_bfloat16 hb = __float2bfloat16(r[j]);
        h[j] = __bfloat16_as_ushort(hb);
        l[j] = __bfloat16_as_ushort(__float2bfloat16(r[j] - __bfloat162float(hb)));
    }
    size_t base = (((size_t)n * HO + py) * HO + px) * 64 + c4 * 4;
    *reinterpret_cast<uint2*>(ohi + base) = make_uint2((uint32_t)h[0] | ((uint32_t)h[1] << 16),
                                                       (uint32_t)h[2] | ((uint32_t)h[3] << 16));
    *reinterpret_cast<uint2*>(olo + base) = make_uint2((uint32_t)l[0] | ((uint32_t)l[1] << 16),
                                                       (uint32_t)l[2] | ((uint32_t)l[3] << 16));
}

// ======================= embed: BN4 + LReLU + global max over 10x10 =======================
__global__ void embed_k() {
    int idx = blockIdx.x * 256 + threadIdx.x;
    if (idx >= NTOT * 64) return;
    int c = idx & 63, n = idx >> 6, g = bn_group(n);
    float sc = g_scale[g * 64 + c], sh = g_shift[g * 64 + c];
    const float* p = g_c4out + (size_t)n * 6400 + c;
    float m = -1e30f;
    for (int i = 0; i < 100; i++) m = fmaxf(m, bnlr(p[(size_t)i * 64], sc, sh));
    g_emb[idx] = m;
}

// ======================= attention over 3 prototypes =======================
__global__ void attn_k(const float* __restrict__ wq, const float* __restrict__ wk,
                       const float* __restrict__ wv, const float* __restrict__ fcw,
                       const float* __restrict__ fcb, const float* __restrict__ lng,
                       const float* __restrict__ lnb) {
    __shared__ float P[3][64], Q[3][64], K[3][64], V[3][64], O[3][64];
    __shared__ float A[3][3], MU[3], SG[3], NR[3];
    int t = threadIdx.x;
    for (int l = 0; l < 3; l++) {
        float s = 0.f;
        for (int i = 0; i < 8; i++) s += g_emb[(NQ + l * 8 + i) * 64 + t];
        P[l][t] = s * 0.125f;
    }
    __syncthreads();
    for (int l = 0; l < 3; l++) {
        float q = 0.f, k = 0.f, v = 0.f;
        for (int d = 0; d < 64; d++) {
            float p = P[l][d];
            q += p * wq[t * 64 + d]; k += p * wk[t * 64 + d]; v += p * wv[t * 64 + d];
        }
        Q[l][t] = q; K[l][t] = k; V[l][t] = v;
    }
    __syncthreads();
    if (t < 9) {
        int qi = t / 3, ki = t % 3;
        float a = 0.f;
        for (int d = 0; d < 64; d++) a += Q[qi][d] * K[ki][d];
        A[qi][ki] = a * 0.125f;
    }
    __syncthreads();
    if (t < 3) {
        float m = fmaxf(A[t][0], fmaxf(A[t][1], A[t][2]));
        float e0 = expf(A[t][0] - m), e1 = expf(A[t][1] - m), e2 = expf(A[t][2] - m);
        float inv = 1.f / (e0 + e1 + e2);
        A[t][0] = e0 * inv; A[t][1] = e1 * inv; A[t][2] = e2 * inv;
    }
    __syncthreads();
    for (int l = 0; l < 3; l++)
        O[l][t] = A[l][0] * V[0][t] + A[l][1] * V[1][t] + A[l][2] * V[2][t];
    __syncthreads();
    for (int l = 0; l < 3; l++) {
        float o = fcb[t];
        for (int d = 0; d < 64; d++) o += O[l][d] * fcw[t * 64 + d];
        Q[l][t] = o + P[l][t];
    }
    __syncthreads();
    if (t < 3) {
        float s = 0.f, q = 0.f;
        for (int d = 0; d < 64; d++) { float x = Q[t][d]; s += x; q += x * x; }
        float m = s / 64.f;
        MU[t] = m;
        SG[t] = rsqrtf(q / 64.f - m * m + EPS_LN);
    }
    __syncthreads();
    for (int l = 0; l < 3; l++)
        K[l][t] = (Q[l][t] - MU[l]) * SG[l] * lng[t] + lnb[t];
    __syncthreads();
    if (t < 3) {
        float q = 0.f;
        for (int d = 0; d < 64; d++) q += K[t][d] * K[t][d];
        NR[t] = rsqrtf(q);
    }
    __syncthreads();
    for (int l = 0; l < 3; l++) g_sn[l * 64 + t] = K[l][t] * NR[l];
}

__global__ void cos_k(float* __restrict__ out) {
    int warp = threadIdx.x >> 5, lane = threadIdx.x & 31;
    int n = blockIdx.x * 4 + warp;
    if (n >= NQ) return;
    float v1 = g_emb[n * 64 + lane], v2 = g_emb[n * 64 + 32 + lane];
    float ss = v1 * v1 + v2 * v2;
#pragma unroll
    for (int o = 16; o > 0; o >>= 1) ss += __shfl_xor_sync(0xffffffffu, ss, o);
    float rn = rsqrtf(ss);
#pragma unroll
    for (int k = 0; k < 3; k++) {
        float d = v1 * g_sn[k * 64 + lane] + v2 * g_sn[k * 64 + 32 + lane];
#pragma unroll
        for (int o = 16; o > 0; o >>= 1) d += __shfl_xor_sync(0xffffffffu, d, o);
        if (lane == 0) out[n * 3 + k] = d * rn;
    }
}

// ======================= launch =======================
extern "C" void kernel_launch(void* const* d_in, const int* in_sizes, int n_in,
                              void* d_out, int out_size) {
    const float* input1  = (const float*)d_in[0];
    const float* input2  = (const float*)d_in[1];
    const float* conv1_w = (const float*)d_in[2];
    const float* conv2_w = (const float*)d_in[3];
    const float* conv3_w = (const float*)d_in[4];
    const float* conv4_w = (const float*)d_in[5];
    const float* bn_g[4] = {(const float*)d_in[6], (const float*)d_in[8], (const float*)d_in[10], (const float*)d_in[12]};
    const float* bn_b[4] = {(const float*)d_in[7], (const float*)d_in[9], (const float*)d_in[11], (const float*)d_in[13]};
    float* out = (float*)d_out;

    const int SM40 = 2 * 7 * 42 * 128;    // 75264
    const int SM20 = 2 * 10 * 22 * 128;   // 56320
    const int SM10 = 2 * 16 * 12 * 128;   // 49152
    cudaFuncSetAttribute(conv_t<40>, cudaFuncAttributeMaxDynamicSharedMemorySize, SM40);
    cudaFuncSetAttribute(conv_t<20>, cudaFuncAttributeMaxDynamicSharedMemorySize, SM20);
    cudaFuncSetAttribute(conv_t<10>, cudaFuncAttributeMaxDynamicSharedMemorySize, SM10);

    unsigned short *wF2, *wF3, *wF4, *ihi, *ilo;
    cudaGetSymbolAddress((void**)&wF2, g_wF2);
    cudaGetSymbolAddress((void**)&wF3, g_wF3);
    cudaGetSymbolAddress((void**)&wF4, g_wF4);
    cudaGetSymbolAddress((void**)&ihi, g_inhi);
    cudaGetSymbolAddress((void**)&ilo, g_inlo);
    float *c1, *c2, *c3, *c4;
    cudaGetSymbolAddress((void**)&c1, g_c1out);
    cudaGetSymbolAddress((void**)&c2, g_c2out);
    cudaGetSymbolAddress((void**)&c3, g_c3out);
    cudaGetSymbolAddress((void**)&c4, g_c4out);

    tw1_k<<<7, 256>>>(conv1_w);
    wcvt_k<<<72, 256>>>(conv2_w, wF2);
    wcvt_k<<<72, 256>>>(conv3_w, wF3);
    wcvt_k<<<72, 256>>>(conv4_w, wF4);

    // L1
    zstats_k<<<1, 512>>>();
    conv1_k<<<dim3(100, NTOT), 256>>>(input1, input2);
    finalize_k<<<1, 256>>>(bn_g[0], bn_b[0], 80);
    bnpool_k<80><<<(NTOT * 40 * 40 * 16 + 255) / 256, 256>>>(c1, ihi, ilo);

    // L2
    zstats_k<<<1, 512>>>();
    conv_t<40><<<NTOT, 256, SM40>>>(ihi, ilo, c2, wF2);
    stats_k<40><<<NTOT, 256>>>(c2);
    finalize_k<<<1, 256>>>(bn_g[1], bn_b[1], 40);
    bnpool_k<40><<<(NTOT * 20 * 20 * 16 + 255) / 256, 256>>>(c2, ihi, ilo);

    // L3
    zstats_k<<<1, 512>>>();
    conv_t<20><<<NTOT, 256, SM20>>>(ihi, ilo, c3, wF3);
    stats_k<20><<<NTOT, 256>>>(c3);
    finalize_k<<<1, 256>>>(bn_g[2], bn_b[2], 20);
    bnpool_k<20><<<(NTOT * 10 * 10 * 16 + 255) / 256, 256>>>(c3, ihi, ilo);

    // L4
    zstats_k<<<1, 512>>>();
    conv_t<10><<<NTOT, 256, SM10>>>(ihi, ilo, c4, wF4);
    stats_k<10><<<NTOT, 256>>>(c4);
    finalize_k<<<1, 256>>>(bn_g[3], bn_b[3], 10);
    embed_k<<<(NTOT * 64 + 255) / 256, 256>>>();

    attn_k<<<1, 64>>>((const float*)d_in[14], (const float*)d_in[15], (const float*)d_in[16],
                      (const float*)d_in[17], (const float*)d_in[18],
                      (const float*)d_in[19], (const float*)d_in[20]);
    cos_k<<<256, 128>>>(out);
}

// round 9
// speedup vs baseline: 2.8044x; 1.2013x over previous
#include <cuda_runtime.h>
#include <cuda_bf16.h>
#include <math.h>
#include <stdint.h>

#define EPS_BN 1e-5f
#define EPS_LN 1e-5f
#define NQ   1024
#define NTOT 1048

// ======================= helpers =======================
__device__ __forceinline__ uint32_t smem_u32(const void* p) {
    uint32_t a;
    asm("{ .reg .u64 t; cvta.to.shared.u64 t, %1; cvt.u32.u64 %0, t; }" : "=r"(a) : "l"(p));
    return a;
}
__device__ __forceinline__ void ldsm4(uint32_t* r, uint32_t addr) {
    asm volatile("ldmatrix.sync.aligned.m8n8.x4.shared.b16 {%0,%1,%2,%3}, [%4];"
                 : "=r"(r[0]), "=r"(r[1]), "=r"(r[2]), "=r"(r[3]) : "r"(addr) : "memory");
}
__device__ __forceinline__ void mma16816(float* d, const uint32_t* a, uint32_t b0, uint32_t b1) {
    asm volatile("mma.sync.aligned.m16n8k16.row.col.f32.bf16.bf16.f32 "
                 "{%0,%1,%2,%3}, {%4,%5,%6,%7}, {%8,%9}, {%0,%1,%2,%3};"
                 : "+f"(d[0]), "+f"(d[1]), "+f"(d[2]), "+f"(d[3])
                 : "r"(a[0]), "r"(a[1]), "r"(a[2]), "r"(a[3]), "r"(b0), "r"(b1));
}

// ======================= scratch (NHWC) =======================
static __device__ float g_c1out[429260800];            // 1048*80*80*64
static __device__ float g_c2out[107315200];
static __device__ float g_c3out[26828800];
static __device__ float g_c4out[6707200];
static __device__ unsigned short g_inhi[107315200];    // bf16 hi image (reused per layer)
static __device__ unsigned short g_inlo[107315200];    // bf16 lo image
static __device__ float g_stats[512];
static __device__ float g_scale[256];
static __device__ float g_shift[256];
static __device__ __align__(16) unsigned short g_wF1[4096];   // L1 frag weights (K=32)
static __device__ __align__(16) unsigned short g_wF2[73728];  // 9*2*4*32*8 entries x 4
static __device__ __align__(16) unsigned short g_wF3[73728];
static __device__ __align__(16) unsigned short g_wF4[73728];
static __device__ float g_emb[NTOT * 64];
static __device__ float g_sn[3 * 64];

__device__ __forceinline__ int bn_group(int n) { return (n < NQ) ? 0 : (1 + ((n - NQ) >> 3)); }

// Epilogue stats flush: per-thread column partials -> warp reduce -> atomics
__device__ __forceinline__ void stats_flush(int n, int lane, int warp_n,
                                            float* s0, float* s1, float* q0, float* q1) {
#pragma unroll
    for (int o = 4; o <= 16; o <<= 1) {
#pragma unroll
        for (int nb = 0; nb < 4; nb++) {
            s0[nb] += __shfl_down_sync(0xffffffffu, s0[nb], o);
            s1[nb] += __shfl_down_sync(0xffffffffu, s1[nb], o);
            q0[nb] += __shfl_down_sync(0xffffffffu, q0[nb], o);
            q1[nb] += __shfl_down_sync(0xffffffffu, q1[nb], o);
        }
    }
    if (lane < 4) {
        int g = bn_group(n);
#pragma unroll
        for (int nb = 0; nb < 4; nb++) {
            int c0 = warp_n * 32 + nb * 8 + lane * 2;
            atomicAdd(&g_stats[(g * 64 + c0) * 2],     s0[nb]);
            atomicAdd(&g_stats[(g * 64 + c0) * 2 + 1], q0[nb]);
            atomicAdd(&g_stats[(g * 64 + c0 + 1) * 2],     s1[nb]);
            atomicAdd(&g_stats[(g * 64 + c0 + 1) * 2 + 1], q1[nb]);
        }
    }
}

// ======================= weight prep =======================
// L1 frag pack + stats zero fused (launch #1).
// conv1_w [64][3][3][3] -> e=[cmb][kk(2)][lane][nb], K=32 (27 real + 5 pad)
__global__ void wcvt1zs_k(const float* __restrict__ w, unsigned short* __restrict__ dst) {
    int e = blockIdx.x * 256 + threadIdx.x;
    if (e < 512) g_stats[e] = 0.f;
    if (e >= 1024) return;
    int nb = e & 7, lane = (e >> 3) & 31, kk = (e >> 8) & 1, cmb = (e >> 9) & 1;
    int n = nb * 8 + (lane >> 2);
#pragma unroll
    for (int j = 0; j < 2; j++)
#pragma unroll
        for (int h = 0; h < 2; h++) {
            int k = kk * 16 + (lane & 3) * 2 + j * 8 + h;
            float x = 0.f;
            if (k < 27) { int ic = k / 9, s = k - ic * 9; x = w[(n * 3 + ic) * 9 + s]; }
            __nv_bfloat16 hi = __float2bfloat16(x);
            unsigned short v;
            if (cmb == 0) v = __bfloat16_as_ushort(hi);
            else          v = __bfloat16_as_ushort(__float2bfloat16(x - __bfloat162float(hi)));
            dst[e * 4 + j * 2 + h] = v;
        }
}
// L2-4: conv_w [oc][64][3][3] -> frag order e=[s][cmb][kk][lane][nb], 4 ushorts each
__global__ void wcvt_k(const float* __restrict__ w, unsigned short* __restrict__ dst) {
    int e = blockIdx.x * 256 + threadIdx.x;
    if (e >= 18432) return;
    int nb = e & 7, lane = (e >> 3) & 31, kk = (e >> 8) & 3, cmb = (e >> 10) & 1, s = e >> 11;
    int n = nb * 8 + (lane >> 2);
#pragma unroll
    for (int j = 0; j < 2; j++)
#pragma unroll
        for (int h = 0; h < 2; h++) {
            int k = kk * 16 + (lane & 3) * 2 + j * 8 + h;
            float x = w[(n * 64 + k) * 9 + s];
            __nv_bfloat16 hi = __float2bfloat16(x);
            unsigned short v;
            if (cmb == 0) v = __bfloat16_as_ushort(hi);
            else          v = __bfloat16_as_ushort(__float2bfloat16(x - __bfloat162float(hi)));
            dst[e * 4 + j * 2 + h] = v;
        }
}
__global__ void zstats_k() { g_stats[threadIdx.x] = 0.f; }

// ======================= L1 via mma.sync (im2col K=32) + fused stats =======================
// No M tail: 6400 = 50*128, so unguarded stats are exact.
__global__ void __launch_bounds__(256) conv1_t(
    const float* __restrict__ in1, const float* __restrict__ in2,
    const unsigned short* __restrict__ wF, int n0)
{
    constexpr int H = 80, NPIX = 6400, NT = 50;
    __shared__ __align__(16) unsigned char sA[128 * 128];   // 128 px x (32 hi + 32 lo) bf16
    const uint32_t sb = smem_u32(sA);
    const int tid = threadIdx.x, lane = tid & 31, wid = tid >> 5;
    const int warp_m = wid & 3, warp_n = wid >> 2;
    const int khalf = lane >> 4;
    const int n = blockIdx.x + n0;
    const float* gin = (n < NQ) ? in1 + (size_t)n * 19200 : in2 + (size_t)(n - NQ) * 19200;
    float* gout = g_c1out + (size_t)n * NPIX * 64;

    float s0[4] = {0,0,0,0}, s1[4] = {0,0,0,0}, q0[4] = {0,0,0,0}, q1[4] = {0,0,0,0};

    for (int t = 0; t < NT; t++) {
        __syncthreads();
        const int m0 = t * 128;
        {
            const int p = tid >> 1, kh = tid & 1;
            const int P = m0 + p, y = P / H, x = P - (P / H) * H;
#define BUILD1(k) { \
            float val = 0.f; \
            if ((k) < 27) { \
                constexpr int ic = (k) / 9, s9 = (k) - ic * 9; \
                constexpr int dy = s9 / 3 - 1, dx = s9 % 3 - 1; \
                int yy = y + dy, xx = x + dx; \
                if ((unsigned)yy < (unsigned)H && (unsigned)xx < (unsigned)H) \
                    val = gin[ic * 6400 + yy * H + xx]; \
            } \
            __nv_bfloat16 hb = __float2bfloat16(val); \
            unsigned short hv = __bfloat16_as_ushort(hb); \
            unsigned short lv = __bfloat16_as_ushort(__float2bfloat16(val - __bfloat162float(hb))); \
            uint32_t oh = (uint32_t)p * 128 + ((((k) >> 3) ^ (p & 7)) << 4) + ((k) & 7) * 2; \
            uint32_t ol = (uint32_t)p * 128 + ((((((k) >> 3) + 4)) ^ (p & 7)) << 4) + ((k) & 7) * 2; \
            *reinterpret_cast<unsigned short*>(sA + oh) = hv; \
            *reinterpret_cast<unsigned short*>(sA + ol) = lv; }
            if (kh == 0) {
                BUILD1(0) BUILD1(1) BUILD1(2) BUILD1(3) BUILD1(4) BUILD1(5) BUILD1(6) BUILD1(7)
                BUILD1(8) BUILD1(9) BUILD1(10) BUILD1(11) BUILD1(12) BUILD1(13) BUILD1(14) BUILD1(15)
            } else {
                BUILD1(16) BUILD1(17) BUILD1(18) BUILD1(19) BUILD1(20) BUILD1(21) BUILD1(22) BUILD1(23)
                BUILD1(24) BUILD1(25) BUILD1(26) BUILD1(27) BUILD1(28) BUILD1(29) BUILD1(30) BUILD1(31)
            }
#undef BUILD1
        }
        __syncthreads();

        float acc[2][4][4];
#pragma unroll
        for (int a = 0; a < 2; a++)
#pragma unroll
            for (int b = 0; b < 4; b++)
#pragma unroll
                for (int c = 0; c < 4; c++) acc[a][b][c] = 0.f;

        const int r0 = warp_m * 32 + (lane & 15);
        const int r1 = r0 + 16;
#pragma unroll
        for (int kk = 0; kk < 2; kk++) {
            const int chh = kk * 2 + khalf, chl = chh + 4;
            uint32_t ah0[4], ah1[4], al0[4], al1[4];
            ldsm4(ah0, sb + (uint32_t)r0 * 128 + ((chh ^ (r0 & 7)) << 4));
            ldsm4(ah1, sb + (uint32_t)r1 * 128 + ((chh ^ (r1 & 7)) << 4));
            ldsm4(al0, sb + (uint32_t)r0 * 128 + ((chl ^ (r0 & 7)) << 4));
            ldsm4(al1, sb + (uint32_t)r1 * 128 + ((chl ^ (r1 & 7)) << 4));

            const unsigned short* bs0 = wF + (((0 + kk) * 32 + lane) * 32 + warp_n * 16);
            const unsigned short* bs1 = wF + (((2 + kk) * 32 + lane) * 32 + warp_n * 16);
            uint4 h0 = *reinterpret_cast<const uint4*>(bs0);
            uint4 h1 = *reinterpret_cast<const uint4*>(bs0 + 8);
            uint4 l0 = *reinterpret_cast<const uint4*>(bs1);
            uint4 l1 = *reinterpret_cast<const uint4*>(bs1 + 8);
            uint32_t bh[8] = {h0.x, h0.y, h0.z, h0.w, h1.x, h1.y, h1.z, h1.w};
            uint32_t bl[8] = {l0.x, l0.y, l0.z, l0.w, l1.x, l1.y, l1.z, l1.w};

#pragma unroll
            for (int nb = 0; nb < 4; nb++) {
                mma16816(acc[0][nb], ah0, bh[nb * 2], bh[nb * 2 + 1]);
                mma16816(acc[1][nb], ah1, bh[nb * 2], bh[nb * 2 + 1]);
            }
#pragma unroll
            for (int nb = 0; nb < 4; nb++) {
                mma16816(acc[0][nb], ah0, bl[nb * 2], bl[nb * 2 + 1]);
                mma16816(acc[1][nb], ah1, bl[nb * 2], bl[nb * 2 + 1]);
            }
#pragma unroll
            for (int nb = 0; nb < 4; nb++) {
                mma16816(acc[0][nb], al0, bh[nb * 2], bh[nb * 2 + 1]);
                mma16816(acc[1][nb], al1, bh[nb * 2], bh[nb * 2 + 1]);
            }
        }

#pragma unroll
        for (int mb = 0; mb < 2; mb++) {
            int p0 = m0 + warp_m * 32 + mb * 16 + (lane >> 2);
#pragma unroll
            for (int nb = 0; nb < 4; nb++) {
                int col = warp_n * 32 + nb * 8 + (lane & 3) * 2;
                *reinterpret_cast<float2*>(gout + (size_t)p0 * 64 + col) =
                    make_float2(acc[mb][nb][0], acc[mb][nb][1]);
                *reinterpret_cast<float2*>(gout + (size_t)(p0 + 8) * 64 + col) =
                    make_float2(acc[mb][nb][2], acc[mb][nb][3]);
                s0[nb] += acc[mb][nb][0] + acc[mb][nb][2];
                s1[nb] += acc[mb][nb][1] + acc[mb][nb][3];
                q0[nb] += acc[mb][nb][0] * acc[mb][nb][0] + acc[mb][nb][2] * acc[mb][nb][2];
                q1[nb] += acc[mb][nb][1] * acc[mb][nb][1] + acc[mb][nb][3] * acc[mb][nb][3];
            }
        }
    }
    stats_flush(n, lane, warp_n, s0, s1, q0, q1);
}

// ======================= tensor conv L2-L4 + fused stats (tail-guarded) =======================
template <int H>
__global__ void __launch_bounds__(256) conv_t(
    const unsigned short* __restrict__ inhi, const unsigned short* __restrict__ inlo,
    float* __restrict__ outbuf, const unsigned short* __restrict__ wBf)
{
    constexpr int NPIX = H * H, W2 = H + 2;
    constexpr int NT = (NPIX + 127) / 128;
    constexpr int RB = (127 + H - 1) / H + 3;
    constexpr int SLOTS = RB * W2;
    constexpr int BANDB = SLOTS * 128;
    extern __shared__ __align__(16) unsigned char smem[];
    const uint32_t sb = smem_u32(smem);
    const int tid = threadIdx.x, lane = tid & 31, wid = tid >> 5;
    const int warp_m = wid & 3, warp_n = wid >> 2;
    const int n = blockIdx.x;
    const unsigned short* ghi = inhi + (size_t)n * NPIX * 64;
    const unsigned short* glo = inlo + (size_t)n * NPIX * 64;
    float* gout = outbuf + (size_t)n * NPIX * 64;

    float s0[4] = {0,0,0,0}, s1[4] = {0,0,0,0}, q0[4] = {0,0,0,0}, q1[4] = {0,0,0,0};

    for (int t = 0; t < NT; t++) {
        __syncthreads();
        const int m0 = t * 128, ytile = m0 / H;
        for (int sl = tid; sl < SLOTS; sl += 256) {
            int r = sl / W2, c = sl - r * W2;
            int y = ytile + r - 1, x = c - 1;
            bool v = ((unsigned)y < (unsigned)H) && ((unsigned)x < (unsigned)H);
            const uint4* sh = reinterpret_cast<const uint4*>(ghi + (size_t)(y * H + x) * 64);
            const uint4* so = reinterpret_cast<const uint4*>(glo + (size_t)(y * H + x) * 64);
#pragma unroll
            for (int ch = 0; ch < 8; ch++) {
                uint4 dh = v ? sh[ch] : make_uint4(0, 0, 0, 0);
                uint4 dl = v ? so[ch] : make_uint4(0, 0, 0, 0);
                uint32_t off = (uint32_t)sl * 128 + (uint32_t)((ch ^ (sl & 7)) << 4);
                *reinterpret_cast<uint4*>(smem + off) = dh;
                *reinterpret_cast<uint4*>(smem + BANDB + off) = dl;
            }
        }
        __syncthreads();

        int bp[2];
#pragma unroll
        for (int mb = 0; mb < 2; mb++) {
            int p = m0 + warp_m * 32 + mb * 16 + (lane & 15);
            int y = p / H, x = p - y * H;
            bp[mb] = (y - ytile + 1) * W2 + x + 1;
        }
        const int khalf = lane >> 4;

        float acc[2][4][4];
#pragma unroll
        for (int a = 0; a < 2; a++)
#pragma unroll
            for (int b = 0; b < 4; b++)
#pragma unroll
                for (int c = 0; c < 4; c++) acc[a][b][c] = 0.f;

#pragma unroll 1
        for (int s = 0; s < 9; s++) {
            const int so9 = (s / 3 - 1) * W2 + (s % 3 - 1);
            const int b0 = bp[0] + so9, b1 = bp[1] + so9;
#pragma unroll
            for (int kk = 0; kk < 4; kk++) {
                const int ch = kk * 2 + khalf;
                uint32_t off0 = (uint32_t)b0 * 128 + (uint32_t)((ch ^ (b0 & 7)) << 4);
                uint32_t off1 = (uint32_t)b1 * 128 + (uint32_t)((ch ^ (b1 & 7)) << 4);
                uint32_t ah0[4], ah1[4], al0[4], al1[4];
                ldsm4(ah0, sb + off0);
                ldsm4(ah1, sb + off1);
                ldsm4(al0, sb + BANDB + off0);
                ldsm4(al1, sb + BANDB + off1);

                const unsigned short* bs0 = wBf + ((((s * 2 + 0) * 4 + kk) * 32 + lane) * 32 + warp_n * 16);
                const unsigned short* bs1 = wBf + ((((s * 2 + 1) * 4 + kk) * 32 + lane) * 32 + warp_n * 16);
                uint4 h0 = *reinterpret_cast<const uint4*>(bs0);
                uint4 h1 = *reinterpret_cast<const uint4*>(bs0 + 8);
                uint4 l0 = *reinterpret_cast<const uint4*>(bs1);
                uint4 l1 = *reinterpret_cast<const uint4*>(bs1 + 8);
                uint32_t bh[8] = {h0.x, h0.y, h0.z, h0.w, h1.x, h1.y, h1.z, h1.w};
                uint32_t bl[8] = {l0.x, l0.y, l0.z, l0.w, l1.x, l1.y, l1.z, l1.w};

#pragma unroll
                for (int nb = 0; nb < 4; nb++) {
                    mma16816(acc[0][nb], ah0, bh[nb * 2], bh[nb * 2 + 1]);
                    mma16816(acc[1][nb], ah1, bh[nb * 2], bh[nb * 2 + 1]);
                }
#pragma unroll
                for (int nb = 0; nb < 4; nb++) {
                    mma16816(acc[0][nb], ah0, bl[nb * 2], bl[nb * 2 + 1]);
                    mma16816(acc[1][nb], ah1, bl[nb * 2], bl[nb * 2 + 1]);
                }
#pragma unroll
                for (int nb = 0; nb < 4; nb++) {
                    mma16816(acc[0][nb], al0, bh[nb * 2], bh[nb * 2 + 1]);
                    mma16816(acc[1][nb], al1, bh[nb * 2], bh[nb * 2 + 1]);
                }
            }
        }

#pragma unroll
        for (int mb = 0; mb < 2; mb++) {
            int p0 = m0 + warp_m * 32 + mb * 16 + (lane >> 2);
#pragma unroll
            for (int nb = 0; nb < 4; nb++) {
                int col = warp_n * 32 + nb * 8 + (lane & 3) * 2;
                if (p0 < NPIX) {
                    *reinterpret_cast<float2*>(gout + (size_t)p0 * 64 + col) =
                        make_float2(acc[mb][nb][0], acc[mb][nb][1]);
                    s0[nb] += acc[mb][nb][0];
                    s1[nb] += acc[mb][nb][1];
                    q0[nb] += acc[mb][nb][0] * acc[mb][nb][0];
                    q1[nb] += acc[mb][nb][1] * acc[mb][nb][1];
                }
                if (p0 + 8 < NPIX) {
                    *reinterpret_cast<float2*>(gout + (size_t)(p0 + 8) * 64 + col) =
                        make_float2(acc[mb][nb][2], acc[mb][nb][3]);
                    s0[nb] += acc[mb][nb][2];
                    s1[nb] += acc[mb][nb][3];
                    q0[nb] += acc[mb][nb][2] * acc[mb][nb][2];
                    q1[nb] += acc[mb][nb][3] * acc[mb][nb][3];
                }
            }
        }
    }
    stats_flush(n, lane, warp_n, s0, s1, q0, q1);
}

__global__ void finalize_k(const float* __restrict__ gam, const float* __restrict__ bet, int H) {
    int t = threadIdx.x, grp = t >> 6, oc = t & 63;
    float cnt = (grp == 0 ? (float)NQ : 8.f) * (float)(H * H);
    float m = g_stats[t * 2] / cnt;
    float v = g_stats[t * 2 + 1] / cnt - m * m;
    float sc = gam[oc] * rsqrtf(v + EPS_BN);
    g_scale[t] = sc;
    g_shift[t] = bet[oc] - m * sc;
}

// ======================= BN + LReLU + pool2 -> bf16 hi/lo NHWC =======================
__device__ __forceinline__ float bnlr(float x, float sc, float sh) {
    x = fmaf(x, sc, sh);
    return x > 0.f ? x : 0.2f * x;
}
template <int HIN>
__global__ void bnpool_k(const float* __restrict__ in,
                         unsigned short* __restrict__ ohi, unsigned short* __restrict__ olo) {
    constexpr int HO = HIN / 2;
    int idx = blockIdx.x * 256 + threadIdx.x;
    if (idx >= NTOT * HO * HO * 16) return;
    int c4 = idx & 15, t = idx >> 4;
    int px = t % HO; t /= HO;
    int py = t % HO;
    int n = t / HO, g = bn_group(n);
    float4 sc = *reinterpret_cast<const float4*>(&g_scale[g * 64 + c4 * 4]);
    float4 sh = *reinterpret_cast<const float4*>(&g_shift[g * 64 + c4 * 4]);
    const float* p = in + (((size_t)n * HIN + 2 * py) * HIN + 2 * px) * 64 + c4 * 4;
    float4 a = *reinterpret_cast<const float4*>(p);
    float4 b = *reinterpret_cast<const float4*>(p + 64);
    float4 c = *reinterpret_cast<const float4*>(p + HIN * 64);
    float4 d = *reinterpret_cast<const float4*>(p + HIN * 64 + 64);
    float r[4];
    r[0] = fmaxf(fmaxf(bnlr(a.x,sc.x,sh.x), bnlr(b.x,sc.x,sh.x)), fmaxf(bnlr(c.x,sc.x,sh.x), bnlr(d.x,sc.x,sh.x)));
    r[1] = fmaxf(fmaxf(bnlr(a.y,sc.y,sh.y), bnlr(b.y,sc.y,sh.y)), fmaxf(bnlr(c.y,sc.y,sh.y), bnlr(d.y,sc.y,sh.y)));
    r[2] = fmaxf(fmaxf(bnlr(a.z,sc.z,sh.z), bnlr(b.z,sc.z,sh.z)), fmaxf(bnlr(c.z,sc.z,sh.z), bnlr(d.z,sc.z,sh.z)));
    r[3] = fmaxf(fmaxf(bnlr(a.w,sc.w,sh.w), bnlr(b.w,sc.w,sh.w)), fmaxf(bnlr(c.w,sc.w,sh.w), bnlr(d.w,sc.w,sh.w)));
    unsigned short h[4], l[4];
#pragma unroll
    for (int j = 0; j < 4; j++) {
        __nv_bfloat16 hb = __float2bfloat16(r[j]);
        h[j] = __bfloat16_as_ushort(hb);
        l[j] = __bfloat16_as_ushort(__float2bfloat16(r[j] - __bfloat162float(hb)));
    }
    size_t base = (((size_t)n * HO + py) * HO + px) * 64 + c4 * 4;
    *reinterpret_cast<uint2*>(ohi + base) = make_uint2((uint32_t)h[0] | ((uint32_t)h[1] << 16),
                                                       (uint32_t)h[2] | ((uint32_t)h[3] << 16));
    *reinterpret_cast<uint2*>(olo + base) = make_uint2((uint32_t)l[0] | ((uint32_t)l[1] << 16),
                                                       (uint32_t)l[2] | ((uint32_t)l[3] << 16));
}

// ======================= embed: BN4 + LReLU + global max over 10x10 =======================
__global__ void embed_k() {
    int idx = blockIdx.x * 256 + threadIdx.x;
    if (idx >= NTOT * 64) return;
    int c = idx & 63, n = idx >> 6, g = bn_group(n);
    float sc = g_scale[g * 64 + c], sh = g_shift[g * 64 + c];
    const float* p = g_c4out + (size_t)n * 6400 + c;
    float m = -1e30f;
    for (int i = 0; i < 100; i++) m = fmaxf(m, bnlr(p[(size_t)i * 64], sc, sh));
    g_emb[idx] = m;
}

// ======================= attention over 3 prototypes =======================
__global__ void attn_k(const float* __restrict__ wq, const float* __restrict__ wk,
                       const float* __restrict__ wv, const float* __restrict__ fcw,
                       const float* __restrict__ fcb, const float* __restrict__ lng,
                       const float* __restrict__ lnb) {
    __shared__ float P[3][64], Q[3][64], K[3][64], V[3][64], O[3][64];
    __shared__ float A[3][3], MU[3], SG[3], NR[3];
    int t = threadIdx.x;
    for (int l = 0; l < 3; l++) {
        float s = 0.f;
        for (int i = 0; i < 8; i++) s += g_emb[(NQ + l * 8 + i) * 64 + t];
        P[l][t] = s * 0.125f;
    }
    __syncthreads();
    for (int l = 0; l < 3; l++) {
        float q = 0.f, k = 0.f, v = 0.f;
        for (int d = 0; d < 64; d++) {
            float p = P[l][d];
            q += p * wq[t * 64 + d]; k += p * wk[t * 64 + d]; v += p * wv[t * 64 + d];
        }
        Q[l][t] = q; K[l][t] = k; V[l][t] = v;
    }
    __syncthreads();
    if (t < 9) {
        int qi = t / 3, ki = t % 3;
        float a = 0.f;
        for (int d = 0; d < 64; d++) a += Q[qi][d] * K[ki][d];
        A[qi][ki] = a * 0.125f;
    }
    __syncthreads();
    if (t < 3) {
        float m = fmaxf(A[t][0], fmaxf(A[t][1], A[t][2]));
        float e0 = expf(A[t][0] - m), e1 = expf(A[t][1] - m), e2 = expf(A[t][2] - m);
        float inv = 1.f / (e0 + e1 + e2);
        A[t][0] = e0 * inv; A[t][1] = e1 * inv; A[t][2] = e2 * inv;
    }
    __syncthreads();
    for (int l = 0; l < 3; l++)
        O[l][t] = A[l][0] * V[0][t] + A[l][1] * V[1][t] + A[l][2] * V[2][t];
    __syncthreads();
    for (int l = 0; l < 3; l++) {
        float o = fcb[t];
        for (int d = 0; d < 64; d++) o += O[l][d] * fcw[t * 64 + d];
        Q[l][t] = o + P[l][t];
    }
    __syncthreads();
    if (t < 3) {
        float s = 0.f, q = 0.f;
        for (int d = 0; d < 64; d++) { float x = Q[t][d]; s += x; q += x * x; }
        float m = s / 64.f;
        MU[t] = m;
        SG[t] = rsqrtf(q / 64.f - m * m + EPS_LN);
    }
    __syncthreads();
    for (int l = 0; l < 3; l++)
        K[l][t] = (Q[l][t] - MU[l]) * SG[l] * lng[t] + lnb[t];
    __syncthreads();
    if (t < 3) {
        float q = 0.f;
        for (int d = 0; d < 64; d++) q += K[t][d] * K[t][d];
        NR[t] = rsqrtf(q);
    }
    __syncthreads();
    for (int l = 0; l < 3; l++) g_sn[l * 64 + t] = K[l][t] * NR[l];
}

__global__ void cos_k(float* __restrict__ out) {
    int warp = threadIdx.x >> 5, lane = threadIdx.x & 31;
    int n = blockIdx.x * 4 + warp;
    if (n >= NQ) return;
    float v1 = g_emb[n * 64 + lane], v2 = g_emb[n * 64 + 32 + lane];
    float ss = v1 * v1 + v2 * v2;
#pragma unroll
    for (int o = 16; o > 0; o >>= 1) ss += __shfl_xor_sync(0xffffffffu, ss, o);
    float rn = rsqrtf(ss);
#pragma unroll
    for (int k = 0; k < 3; k++) {
        float d = v1 * g_sn[k * 64 + lane] + v2 * g_sn[k * 64 + 32 + lane];
#pragma unroll
        for (int o = 16; o > 0; o >>= 1) d += __shfl_xor_sync(0xffffffffu, d, o);
        if (lane == 0) out[n * 3 + k] = d * rn;
    }
}

// ======================= launch =======================
extern "C" void kernel_launch(void* const* d_in, const int* in_sizes, int n_in,
                              void* d_out, int out_size) {
    const float* input1  = (const float*)d_in[0];
    const float* input2  = (const float*)d_in[1];
    const float* conv1_w = (const float*)d_in[2];
    const float* conv2_w = (const float*)d_in[3];
    const float* conv3_w = (const float*)d_in[4];
    const float* conv4_w = (const float*)d_in[5];
    const float* bn_g[4] = {(const float*)d_in[6], (const float*)d_in[8], (const float*)d_in[10], (const float*)d_in[12]};
    const float* bn_b[4] = {(const float*)d_in[7], (const float*)d_in[9], (const float*)d_in[11], (const float*)d_in[13]};
    float* out = (float*)d_out;

    const int SM40 = 2 * 7 * 42 * 128;    // 75264
    const int SM20 = 2 * 10 * 22 * 128;   // 56320
    const int SM10 = 2 * 16 * 12 * 128;   // 49152
    cudaFuncSetAttribute(conv_t<40>, cudaFuncAttributeMaxDynamicSharedMemorySize, SM40);
    cudaFuncSetAttribute(conv_t<20>, cudaFuncAttributeMaxDynamicSharedMemorySize, SM20);
    cudaFuncSetAttribute(conv_t<10>, cudaFuncAttributeMaxDynamicSharedMemorySize, SM10);

    unsigned short *wF1, *wF2, *wF3, *wF4, *ihi, *ilo;
    cudaGetSymbolAddress((void**)&wF1, g_wF1);
    cudaGetSymbolAddress((void**)&wF2, g_wF2);
    cudaGetSymbolAddress((void**)&wF3, g_wF3);
    cudaGetSymbolAddress((void**)&wF4, g_wF4);
    cudaGetSymbolAddress((void**)&ihi, g_inhi);
    cudaGetSymbolAddress((void**)&ilo, g_inlo);
    float *c1, *c2, *c3, *c4;
    cudaGetSymbolAddress((void**)&c1, g_c1out);
    cudaGetSymbolAddress((void**)&c2, g_c2out);
    cudaGetSymbolAddress((void**)&c3, g_c3out);
    cudaGetSymbolAddress((void**)&c4, g_c4out);

    // Launch 1: L1 weight frag pack + stats zero. Launches 2-4: conv1_t slices
    // (ncu captures the 4th launch of the process -> conv1_t profile next round).
    wcvt1zs_k<<<4, 256>>>(conv1_w, wF1);
    conv1_t<<<350, 256>>>(input1, input2, wF1, 0);
    conv1_t<<<350, 256>>>(input1, input2, wF1, 350);
    conv1_t<<<348, 256>>>(input1, input2, wF1, 700);
    wcvt_k<<<72, 256>>>(conv2_w, wF2);
    wcvt_k<<<72, 256>>>(conv3_w, wF3);
    wcvt_k<<<72, 256>>>(conv4_w, wF4);
    finalize_k<<<1, 256>>>(bn_g[0], bn_b[0], 80);
    bnpool_k<80><<<(NTOT * 40 * 40 * 16 + 255) / 256, 256>>>(c1, ihi, ilo);

    // L2
    zstats_k<<<1, 512>>>();
    conv_t<40><<<NTOT, 256, SM40>>>(ihi, ilo, c2, wF2);
    finalize_k<<<1, 256>>>(bn_g[1], bn_b[1], 40);
    bnpool_k<40><<<(NTOT * 20 * 20 * 16 + 255) / 256, 256>>>(c2, ihi, ilo);

    // L3
    zstats_k<<<1, 512>>>();
    conv_t<20><<<NTOT, 256, SM20>>>(ihi, ilo, c3, wF3);
    finalize_k<<<1, 256>>>(bn_g[2], bn_b[2], 20);
    bnpool_k<20><<<(NTOT * 10 * 10 * 16 + 255) / 256, 256>>>(c3, ihi, ilo);

    // L4
    zstats_k<<<1, 512>>>();
    conv_t<10><<<NTOT, 256, SM10>>>(ihi, ilo, c4, wF4);
    finalize_k<<<1, 256>>>(bn_g[3], bn_b[3], 10);
    embed_k<<<(NTOT * 64 + 255) / 256, 256>>>();

    attn_k<<<1, 64>>>((const float*)d_in[14], (const float*)d_in[15], (const float*)d_in[16],
                      (const float*)d_in[17], (const float*)d_in[18],
                      (const float*)d_in[19], (const float*)d_in[20]);
    cos_k<<<256, 128>>>(out);
}